// round 2
// baseline (speedup 1.0000x reference)
#include <cuda_runtime.h>
#include <cstdint>
#include <cstddef>

// Problem constants
#define NUM_LUT 3
#define GDIM    1024      // G = IN_F / VEC
#define OUTF    4096
#define SLUT    16
#define VEC     4
#define NGRP    32        // NG = IN_F / GROUP

// Tiling
#define OTILE    128      // o rows per block
#define GTILE    32       // g columns per block (GTILE * VEC == GROUP -> one quant group per block)
#define NTHREADS 256      // 2 threads per o row, each owns 16 consecutive g's

__global__ void __launch_bounds__(NTHREADS)
recon_kernel(const float* __restrict__ gate,
             const float* __restrict__ codebook,
             const float* __restrict__ scales,
             const int*   __restrict__ zeros,
             float*       __restrict__ out)
{
    // Codebook slice for this block: [NUM_LUT][GTILE][SLUT][VEC] = 24 KB
    __shared__ float cb[NUM_LUT * GTILE * SLUT * VEC];

    const int o0  = blockIdx.x * OTILE;
    const int g0  = blockIdx.y * GTILE;
    const int ng  = blockIdx.y;            // quant group index (GTILE*VEC == 128 == GROUP)
    const int tid = threadIdx.x;

    // Stage codebook: per lut, rows [g0, g0+GTILE) of 64 floats each, contiguous
    {
        float4* cbv = reinterpret_cast<float4*>(cb);
        #pragma unroll
        for (int l = 0; l < NUM_LUT; ++l) {
            const float4* src = reinterpret_cast<const float4*>(
                codebook + ((size_t)l * GDIM + g0) * (SLUT * VEC));
            #pragma unroll
            for (int i = tid; i < GTILE * SLUT; i += NTHREADS)
                cbv[l * GTILE * SLUT + i] = src[i];
        }
    }
    __syncthreads();

    const int o_local = tid & (OTILE - 1);   // lanes in a warp -> consecutive o (coalesced gate reads)
    const int half    = tid >> 7;            // 0 or 1: which 16-g sub-range this thread owns
    const int o       = o0 + o_local;

    const float sc = scales[o * NGRP + ng];
    const float zz = (float)zeros[o * NGRP + ng];

    float4* outp = reinterpret_cast<float4*>(out + (size_t)o * (GDIM * VEC));

    const int gl_base = half * 16;

    // Base gate pointers for (l, g0+gl_base, o); advancing g by 1 = +OUTF*SLUT floats
    const float4* qbase0 = reinterpret_cast<const float4*>(
        gate + (((size_t)0 * GDIM + (g0 + gl_base)) * OUTF + o) * SLUT);
    const float4* qbase1 = reinterpret_cast<const float4*>(
        gate + (((size_t)1 * GDIM + (g0 + gl_base)) * OUTF + o) * SLUT);
    const float4* qbase2 = reinterpret_cast<const float4*>(
        gate + (((size_t)2 * GDIM + (g0 + gl_base)) * OUTF + o) * SLUT);
    const size_t gstride = (size_t)OUTF * SLUT / 4;   // float4 stride per g step

    const float* cb0 = &cb[(0 * GTILE + gl_base) * SLUT * VEC];
    const float* cb1 = &cb[(1 * GTILE + gl_base) * SLUT * VEC];
    const float* cb2 = &cb[(2 * GTILE + gl_base) * SLUT * VEC];

    #pragma unroll 2
    for (int j = 0; j < 16; ++j) {
        const float4* qp0 = qbase0 + (size_t)j * gstride;
        const float4* qp1 = qbase1 + (size_t)j * gstride;
        const float4* qp2 = qbase2 + (size_t)j * gstride;

        // Issue all 12 streaming loads up front for MLP
        float4 a0 = __ldcs(qp0 + 0), b0 = __ldcs(qp0 + 1), c0 = __ldcs(qp0 + 2), d0 = __ldcs(qp0 + 3);
        float4 a1 = __ldcs(qp1 + 0), b1 = __ldcs(qp1 + 1), c1 = __ldcs(qp1 + 2), d1 = __ldcs(qp1 + 3);
        float4 a2 = __ldcs(qp2 + 0), b2 = __ldcs(qp2 + 1), c2 = __ldcs(qp2 + 2), d2 = __ldcs(qp2 + 3);

        float4 acc = make_float4(-zz, -zz, -zz, -zz);

        // lut 0 — first-max scan matches jnp.argmax tie semantics exactly
        {
            float q[SLUT] = {a0.x,a0.y,a0.z,a0.w, b0.x,b0.y,b0.z,b0.w,
                             c0.x,c0.y,c0.z,c0.w, d0.x,d0.y,d0.z,d0.w};
            float m = q[0]; int idx = 0;
            #pragma unroll
            for (int s = 1; s < SLUT; ++s) if (q[s] > m) { m = q[s]; idx = s; }
            const float4 cv = *reinterpret_cast<const float4*>(
                cb0 + (j * SLUT + idx) * VEC);
            acc.x += cv.x; acc.y += cv.y; acc.z += cv.z; acc.w += cv.w;
        }
        // lut 1
        {
            float q[SLUT] = {a1.x,a1.y,a1.z,a1.w, b1.x,b1.y,b1.z,b1.w,
                             c1.x,c1.y,c1.z,c1.w, d1.x,d1.y,d1.z,d1.w};
            float m = q[0]; int idx = 0;
            #pragma unroll
            for (int s = 1; s < SLUT; ++s) if (q[s] > m) { m = q[s]; idx = s; }
            const float4 cv = *reinterpret_cast<const float4*>(
                cb1 + (j * SLUT + idx) * VEC);
            acc.x += cv.x; acc.y += cv.y; acc.z += cv.z; acc.w += cv.w;
        }
        // lut 2
        {
            float q[SLUT] = {a2.x,a2.y,a2.z,a2.w, b2.x,b2.y,b2.z,b2.w,
                             c2.x,c2.y,c2.z,c2.w, d2.x,d2.y,d2.z,d2.w};
            float m = q[0]; int idx = 0;
            #pragma unroll
            for (int s = 1; s < SLUT; ++s) if (q[s] > m) { m = q[s]; idx = s; }
            const float4 cv = *reinterpret_cast<const float4*>(
                cb2 + (j * SLUT + idx) * VEC);
            acc.x += cv.x; acc.y += cv.y; acc.z += cv.z; acc.w += cv.w;
        }

        acc.x *= sc; acc.y *= sc; acc.z *= sc; acc.w *= sc;
        // Thread-sequential 16B stores are address-contiguous across j
        // -> sectors/lines merge in L2, clean 67 MB writeback
        __stcs(outp + (g0 + gl_base + j), acc);
    }
}

extern "C" void kernel_launch(void* const* d_in, const int* in_sizes, int n_in,
                              void* d_out, int out_size) {
    const float* gate     = (const float*)d_in[0];  // [3,1024,4096,16] f32
    const float* codebook = (const float*)d_in[1];  // [3,1024,16,4]   f32
    const float* scales   = (const float*)d_in[2];  // [4096,32]       f32
    const int*   zeros    = (const int*)  d_in[3];  // [4096,32]       i32
    float*       out      = (float*)d_out;          // [4096,4096]     f32

    (void)in_sizes; (void)n_in; (void)out_size;

    dim3 grid(OUTF / OTILE, GDIM / GTILE);  // (32, 32) = 1024 blocks
    recon_kernel<<<grid, NTHREADS>>>(gate, codebook, scales, zeros, out);
}

// round 4
// speedup vs baseline: 1.2894x; 1.2894x over previous
#include <cuda_runtime.h>
#include <cstdint>
#include <cstddef>

// Problem constants
#define NUM_LUT 3
#define GDIM    1024      // G = IN_F / VEC
#define OUTF    4096
#define SLUT    16
#define VEC     4
#define NGRP    32        // NG = IN_F / GROUP (GROUP = 32 g's)

// Tiling: block = 8 warps; each warp owns 8 consecutive o's; block loops 8 g's.
#define NTHREADS 256
#define O_PER_WARP 8
#define OTILE (8 * O_PER_WARP)   // 64 o per block
#define GTILE_J 8                // g's per block (8 | 32 -> single quant group)

__global__ void __launch_bounds__(NTHREADS)
recon_kernel(const float* __restrict__ gate,
             const float* __restrict__ codebook,
             const float* __restrict__ scales,
             const int*   __restrict__ zeros,
             float*       __restrict__ out)
{
    const int tid    = threadIdx.x;
    const int wid    = tid >> 5;
    const int lane   = tid & 31;
    const int part   = lane & 3;          // which 16B quarter of the 64B gate row
    const int o_sub  = lane >> 2;         // which of the warp's 8 o's

    const int o0     = blockIdx.x * OTILE + wid * O_PER_WARP;  // warp's first o
    const int o      = o0 + o_sub;
    const int g0     = blockIdx.y * GTILE_J;
    const int ng     = blockIdx.y >> 2;   // quant group (8*4 = 32 g's per group)

    const float sc = scales[o * NGRP + ng];
    const float zz = (float)zeros[o * NGRP + ng];

    // Gate base pointers (float4 units). For fixed (l,g), rows of 16 floats per o;
    // warp covers o0..o0+7 -> 512B contiguous; lane q reads float4 #q.
    // float4 stride per g step: OUTF*SLUT/4 = 16384.
    const float4* gp0 = reinterpret_cast<const float4*>(gate) +
        (((size_t)0 * GDIM + g0) * OUTF + o0) * (SLUT / 4) + lane;
    const float4* gp1 = reinterpret_cast<const float4*>(gate) +
        (((size_t)1 * GDIM + g0) * OUTF + o0) * (SLUT / 4) + lane;
    const float4* gp2 = reinterpret_cast<const float4*>(gate) +
        (((size_t)2 * GDIM + g0) * OUTF + o0) * (SLUT / 4) + lane;
    const size_t gstep = (size_t)OUTF * SLUT / 4;   // 16384 float4 per g

    // Codebook base (floats): entry (l,g,idx,part)
    const float* cbk = codebook;

    float* outrow = out + (size_t)o * (GDIM * VEC) + part;  // + g*4 per step

    #pragma unroll 2
    for (int j = 0; j < GTILE_J; ++j) {
        const int g = g0 + j;

        // Issue all three contiguous 512B loads up front (streaming, no reuse)
        const float4 v0 = __ldcs(gp0 + (size_t)j * gstep);
        const float4 v1 = __ldcs(gp1 + (size_t)j * gstep);
        const float4 v2 = __ldcs(gp2 + (size_t)j * gstep);

        float acc = 0.0f;

        // ---- lut 0 ----
        {
            float m = v0.x; int mi = 0;
            if (v0.y > m) { m = v0.y; mi = 1; }
            if (v0.z > m) { m = v0.z; mi = 2; }
            if (v0.w > m) { m = v0.w; mi = 3; }
            mi += part * 4;
            #pragma unroll
            for (int d = 1; d <= 2; d <<= 1) {
                float om = __shfl_xor_sync(0xffffffffu, m,  d);
                int   oi = __shfl_xor_sync(0xffffffffu, mi, d);
                if (om > m || (om == m && oi < mi)) { m = om; mi = oi; }
            }
            acc += __ldg(cbk + (((size_t)0 * GDIM + g) * SLUT + mi) * VEC + part);
        }
        // ---- lut 1 ----
        {
            float m = v1.x; int mi = 0;
            if (v1.y > m) { m = v1.y; mi = 1; }
            if (v1.z > m) { m = v1.z; mi = 2; }
            if (v1.w > m) { m = v1.w; mi = 3; }
            mi += part * 4;
            #pragma unroll
            for (int d = 1; d <= 2; d <<= 1) {
                float om = __shfl_xor_sync(0xffffffffu, m,  d);
                int   oi = __shfl_xor_sync(0xffffffffu, mi, d);
                if (om > m || (om == m && oi < mi)) { m = om; mi = oi; }
            }
            acc += __ldg(cbk + (((size_t)1 * GDIM + g) * SLUT + mi) * VEC + part);
        }
        // ---- lut 2 ----
        {
            float m = v2.x; int mi = 0;
            if (v2.y > m) { m = v2.y; mi = 1; }
            if (v2.z > m) { m = v2.z; mi = 2; }
            if (v2.w > m) { m = v2.w; mi = 3; }
            mi += part * 4;
            #pragma unroll
            for (int d = 1; d <= 2; d <<= 1) {
                float om = __shfl_xor_sync(0xffffffffu, m,  d);
                int   oi = __shfl_xor_sync(0xffffffffu, mi, d);
                if (om > m || (om == m && oi < mi)) { m = om; mi = oi; }
            }
            acc += __ldg(cbk + (((size_t)2 * GDIM + g) * SLUT + mi) * VEC + part);
        }

        // Dequantize; lane owns one output component. Quad writes 16B contiguous;
        // over the 8-g tile each quad fills its 128B output line -> clean L2 merge.
        __stcs(outrow + g * VEC, (acc - zz) * sc);
    }
}

extern "C" void kernel_launch(void* const* d_in, const int* in_sizes, int n_in,
                              void* d_out, int out_size) {
    const float* gate     = (const float*)d_in[0];  // [3,1024,4096,16] f32
    const float* codebook = (const float*)d_in[1];  // [3,1024,16,4]   f32
    const float* scales   = (const float*)d_in[2];  // [4096,32]       f32
    const int*   zeros    = (const int*)  d_in[3];  // [4096,32]       i32
    float*       out      = (float*)d_out;          // [4096,4096]     f32

    (void)in_sizes; (void)n_in; (void)out_size;

    dim3 grid(OUTF / OTILE, GDIM / GTILE_J);   // (64, 128) = 8192 blocks
    recon_kernel<<<grid, NTHREADS>>>(gate, codebook, scales, zeros, out);
}